// round 2
// baseline (speedup 1.0000x reference)
#include <cuda_runtime.h>
#include <cuda_bf16.h>

// Problem: echo state network.
//   x (256,28,28) f32, W_in (128,28), W_res (128,128), W_out (10,128), b_out (10)
//   proj = x.reshape(7168,28) @ W_in^T                    (7168,128)
//   h_{t+1} = tanh(proj_t + W_res @ h_t)   t = 0..7167, single threaded state
//   h_last[b] = h after step b*28+27 ;  out = h_last @ W_out^T + b_out  (256,10)

#define HIDDEN   128
#define T_STEPS  7168   // 256*28
#define SEQ      28
#define BATCH    256
#define NOUT     10

typedef unsigned long long ull;

// -------- scratch (no allocations allowed) --------
__device__ float g_proj[T_STEPS * HIDDEN];    // 3.67 MB, lives in L2 during scan
__device__ float g_hlast[BATCH * HIDDEN];

// -------- packed f32x2 helpers (sm_100+) --------
__device__ __forceinline__ ull pack2(float lo, float hi) {
    ull r;
    asm("mov.b64 %0, {%1, %2};" : "=l"(r) : "f"(lo), "f"(hi));
    return r;
}
__device__ __forceinline__ void unpack2(ull v, float& lo, float& hi) {
    asm("mov.b64 {%0, %1}, %2;" : "=f"(lo), "=f"(hi) : "l"(v));
}
__device__ __forceinline__ ull ffma2(ull a, ull b, ull c) {
    ull d;
    asm("fma.rn.f32x2 %0, %1, %2, %3;" : "=l"(d) : "l"(a), "l"(b), "l"(c));
    return d;
}
__device__ __forceinline__ ull fadd2(ull a, ull b) {
    ull d;
    asm("add.rn.f32x2 %0, %1, %2;" : "=l"(d) : "l"(a), "l"(b));
    return d;
}

// Accurate-enough tanh: (e^{2x}-1)/(e^{2x}+1) via EX2. |abs err| ~1e-7.
__device__ __forceinline__ float tanh_fast(float x) {
    x = fminf(fmaxf(x, -15.0f), 15.0f);          // avoid inf/inf
    float e = exp2f(x * 2.885390081777927f);     // e^{2x}
    return __fdividef(e - 1.0f, e + 1.0f);
}

// ============================================================
// Kernel 1: proj = x @ W_in^T   (grid of blocks, trivially parallel)
// Each block: 128 threads (one per hidden unit), handles 128 timesteps.
// ============================================================
__global__ __launch_bounds__(128) void proj_kernel(
    const float* __restrict__ x, const float* __restrict__ W_in)
{
    __shared__ float sw[HIDDEN * SEQ];   // W_in, 14 KB
    int i = threadIdx.x;
    for (int k = i; k < HIDDEN * SEQ; k += 128) sw[k] = W_in[k];
    __syncthreads();

    int t0 = blockIdx.x * 128;
    for (int t = t0; t < t0 + 128; t++) {
        const float* xr = x + t * SEQ;
        float a = 0.f;
        #pragma unroll
        for (int d = 0; d < SEQ; d++)
            a = fmaf(xr[d], sw[i * SEQ + d], a);
        g_proj[t * HIDDEN + i] = a;
    }
}

// ============================================================
// Kernel 2: the sequential scan. ONE block, 128 threads.
// Thread i owns output h[i]; its W_res row lives in 64 packed regs.
// h double-buffered in shared; one __syncthreads per step.
// ============================================================
__global__ __launch_bounds__(128, 1) void scan_kernel(
    const float* __restrict__ W_res)
{
    __shared__ __align__(16) float hbuf[2][HIDDEN];
    const int i = threadIdx.x;

    // Load my W_res row, packed as 64 f32x2
    ull w[64];
    {
        const float2* wrow = (const float2*)(W_res + i * HIDDEN);
        #pragma unroll
        for (int j = 0; j < 64; j++) {
            float2 v = wrow[j];
            w[j] = pack2(v.x, v.y);
        }
    }
    hbuf[0][i] = 0.f;
    __syncthreads();

    // proj prefetch pipeline (depth 2) — covers the L2 hit latency
    float pc = g_proj[i];
    float pn = g_proj[HIDDEN + i];
    int cnt = 0;
    int batch = 0;

    for (int t = 0; t < T_STEPS; t++) {
        float pf = (t + 2 < T_STEPS) ? g_proj[(t + 2) * HIDDEN + i] : 0.f;

        const ulonglong2* h2 = (const ulonglong2*)hbuf[t & 1];

        ull acc[8];
        acc[0] = pack2(pc, 0.f);
        #pragma unroll
        for (int k = 1; k < 8; k++) acc[k] = 0ull;   // bits of (0.f,0.f)

        // 32 x LDS.128 + 64 x FFMA2
        #pragma unroll
        for (int j = 0; j < 32; j++) {
            ulonglong2 hv = h2[j];
            acc[(2 * j) & 7]     = ffma2(w[2 * j],     hv.x, acc[(2 * j) & 7]);
            acc[(2 * j + 1) & 7] = ffma2(w[2 * j + 1], hv.y, acc[(2 * j + 1) & 7]);
        }

        // reduce 8 packed accumulators -> scalar
        ull s01 = fadd2(acc[0], acc[4]);
        ull s23 = fadd2(acc[1], acc[5]);
        ull s45 = fadd2(acc[2], acc[6]);
        ull s67 = fadd2(acc[3], acc[7]);
        ull sa  = fadd2(s01, s23);
        ull sb  = fadd2(s45, s67);
        ull st  = fadd2(sa, sb);
        float lo, hi;
        unpack2(st, lo, hi);
        float hn = tanh_fast(lo + hi);

        hbuf[(t + 1) & 1][i] = hn;

        // end of a batch's 28 steps -> record state (off critical path)
        if (++cnt == SEQ) {
            cnt = 0;
            g_hlast[batch * HIDDEN + i] = hn;
            batch++;
        }

        pc = pn;
        pn = pf;
        __syncthreads();
    }
}

// ============================================================
// Kernel 3: out = h_last @ W_out^T + b_out   (256 x 10)
// ============================================================
__global__ __launch_bounds__(128) void out_kernel(
    const float* __restrict__ W_out, const float* __restrict__ b_out,
    float* __restrict__ out)
{
    int tid = blockIdx.x * blockDim.x + threadIdx.x;
    if (tid >= BATCH * NOUT) return;
    int b = tid / NOUT;
    int o = tid % NOUT;
    const float* hr = g_hlast + b * HIDDEN;
    const float* wr = W_out + o * HIDDEN;
    float a = b_out[o];
    #pragma unroll 8
    for (int h = 0; h < HIDDEN; h++)
        a = fmaf(hr[h], wr[h], a);
    out[tid] = a;
}

// ============================================================
extern "C" void kernel_launch(void* const* d_in, const int* in_sizes, int n_in,
                              void* d_out, int out_size)
{
    const float* x     = (const float*)d_in[0];   // 256*28*28
    const float* W_in  = (const float*)d_in[1];   // 128*28
    const float* W_res = (const float*)d_in[2];   // 128*128
    const float* W_out = (const float*)d_in[3];   // 10*128
    const float* b_out = (const float*)d_in[4];   // 10
    float* out = (float*)d_out;                   // 256*10

    proj_kernel<<<T_STEPS / 128, 128>>>(x, W_in);
    scan_kernel<<<1, 128>>>(W_res);
    out_kernel<<<(BATCH * NOUT + 127) / 128, 128>>>(W_out, b_out, out);
}